// round 5
// baseline (speedup 1.0000x reference)
#include <cuda_runtime.h>
#include <cuda_bf16.h>

#define N_NODES 100000
#define N_EDGES 3200000
#define IN_DIM  128
#define HID     64

#define SCAN_ELEMS 512                       // elements per scan1 block (256 thr x 2)
#define SCAN_NB ((N_NODES + SCAN_ELEMS - 1) / SCAN_ELEMS)   // 196
#define SCAN3_NB ((N_NODES + 255) / 256)     // 391

#define GEMM_TILES   (N_NODES / 32)          // 3125
#define HIST_BLKS    (N_EDGES / 256)         // 12500
#define SCAT_BLKS    (N_EDGES / 256)         // 12500
// gemm tile chunk sizes co-scheduled with build kernels
#define G_K2 700
#define G_K3 150
#define G_K4 150
#define G_K5 150
#define G_K6 (GEMM_TILES - G_K2 - G_K3 - G_K4 - G_K5)   // 1975

// ---------------- scratch ----------------
__device__ int    g_is64;
__device__ int    g_deg[N_NODES];
__device__ float  g_dinv[N_NODES];
__device__ int    g_rowptr[N_NODES + 1];
__device__ int    g_cursor[N_NODES];
__device__ int    g_scan[N_NODES];
__device__ int    g_bsum[SCAN_NB];
__device__ int    g_boff[SCAN_NB];
__device__ int    g_csr[N_EDGES];            // src index only
__device__ float  g_h1[N_NODES * HID];       // x @ W1^T (then scaled by dinv)
__device__ float  g_z[N_NODES];              // z' = dinv * (a1 . w)
__device__ float  g_w[HID];                  // w = W2^T @ Wc
__device__ float  g_cb;                      // b2.Wc + bc

__device__ __forceinline__ int edge_at(const void* ei, long long idx) {
    if (g_is64) return (int)((const long long*)ei)[idx];
    return ((const int*)ei)[idx];
}

// ---------------- gemm1 tile (32 nodes x 64 out, K=128), UNscaled output ----------------
__device__ __forceinline__ void gemm1_tile(int tile,
                                           const float* __restrict__ X,
                                           const float* __restrict__ W) {
    __shared__ __align__(16) float Ws[64 * 66];
    __shared__ __align__(16) float Xs[32 * 64];
    const int tid  = threadIdx.x;
    const int warp = tid >> 5, lane = tid & 31;
    const int node0 = tile * 32;

    float2 acc[4];
    #pragma unroll
    for (int r = 0; r < 4; r++) acc[r] = make_float2(0.f, 0.f);

    #pragma unroll
    for (int kt = 0; kt < IN_DIM; kt += 64) {
        #pragma unroll
        for (int i = tid; i < 64 * 64; i += 256) {
            int o = i >> 6, kk = i & 63;
            Ws[kk * 66 + o] = W[o * IN_DIM + kt + kk];
        }
        #pragma unroll
        for (int i = tid; i < 32 * 64; i += 256) {
            int nl = i >> 6, kk = i & 63;
            Xs[nl * 64 + kk] = X[(node0 + nl) * IN_DIM + kt + kk];
        }
        __syncthreads();
        #pragma unroll 8
        for (int kk = 0; kk < 64; kk++) {
            float2 w = *(const float2*)&Ws[kk * 66 + 2 * lane];
            #pragma unroll
            for (int r = 0; r < 4; r++) {
                float xv = Xs[(warp * 4 + r) * 64 + kk];
                acc[r].x = fmaf(xv, w.x, acc[r].x);
                acc[r].y = fmaf(xv, w.y, acc[r].y);
            }
        }
        __syncthreads();
    }
    #pragma unroll
    for (int r = 0; r < 4; r++) {
        int node = node0 + warp * 4 + r;
        ((float2*)g_h1)[node * 32 + lane] = acc[r];
    }
}

// ---------------- K1: init degrees + dtype probe + classifier fold ----------------
__global__ void k1_init(const unsigned* __restrict__ ei32,
                        const float* __restrict__ W2, const float* __restrict__ b2,
                        const float* __restrict__ Wc, const float* __restrict__ bc) {
    int b = blockIdx.x, tid = threadIdx.x;
    if (b < SCAN3_NB) {
        int i = b * 256 + tid;
        if (i < N_NODES) g_deg[i] = 1;
    } else if (b == SCAN3_NB) {
        if (tid == 0) {
            unsigned o = 0;
            #pragma unroll
            for (int i = 1; i < 128; i += 2) o |= ei32[i];
            g_is64 = (o == 0) ? 1 : 0;
        }
    } else {
        if (tid < HID) {
            float s = 0.f;
            #pragma unroll
            for (int j = 0; j < HID; j++) s = fmaf(Wc[j], W2[j * HID + tid], s);
            g_w[tid] = s;
            if (tid == 0) {
                float c = bc[0];
                #pragma unroll
                for (int j = 0; j < HID; j++) c = fmaf(b2[j], Wc[j], c);
                g_cb = c;
            }
        }
    }
}

// ---------------- K2: hist | gemm chunk 1 ----------------
__global__ void k2_hist_gemm(const void* __restrict__ ei,
                             const float* __restrict__ x, const float* __restrict__ W1) {
    if (blockIdx.x < HIST_BLKS) {
        int e = blockIdx.x * 256 + threadIdx.x;
        int d = edge_at(ei, (long long)N_EDGES + e);
        atomicAdd(&g_deg[d], 1);
    } else {
        gemm1_tile(blockIdx.x - HIST_BLKS, x, W1);
    }
}

// ---------------- K3: scan1 (256thr x 2 elems) | gemm chunk 2 ----------------
__global__ void k3_scan1_gemm(const float* __restrict__ x, const float* __restrict__ W1) {
    if (blockIdx.x < SCAN_NB) {
        __shared__ int wsum[8];
        const int tid = threadIdx.x, lane = tid & 31, warp = tid >> 5;
        const int base = blockIdx.x * SCAN_ELEMS + tid * 2;
        int d0 = (base     < N_NODES) ? (g_deg[base]     - 1) : 0;
        int d1 = (base + 1 < N_NODES) ? (g_deg[base + 1] - 1) : 0;
        int v = d0 + d1;
        int s = v;
        #pragma unroll
        for (int o = 1; o < 32; o <<= 1) {
            int t = __shfl_up_sync(0xffffffffu, s, o);
            if (lane >= o) s += t;
        }
        if (lane == 31) wsum[warp] = s;
        __syncthreads();
        if (warp == 0) {
            int ws = (lane < 8) ? wsum[lane] : 0;
            #pragma unroll
            for (int o = 1; o < 8; o <<= 1) {
                int t = __shfl_up_sync(0xffffffffu, ws, o);
                if (lane >= o) ws += t;
            }
            if (lane < 8) wsum[lane] = ws;
        }
        __syncthreads();
        int excl = s - v + (warp ? wsum[warp - 1] : 0);
        if (base     < N_NODES) g_scan[base]     = excl;
        if (base + 1 < N_NODES) g_scan[base + 1] = excl + d0;
        if (tid == 255) g_bsum[blockIdx.x] = excl + v;
    } else {
        gemm1_tile(blockIdx.x - SCAN_NB + G_K2, x, W1);
    }
}

// ---------------- K4: scan2 (1 block) | gemm chunk 3 ----------------
__global__ void k4_scan2_gemm(const float* __restrict__ x, const float* __restrict__ W1) {
    if (blockIdx.x == 0) {
        __shared__ int sh[256];
        const int t = threadIdx.x;
        int v0 = (t < SCAN_NB) ? g_bsum[t] : 0;
        sh[t] = v0;
        __syncthreads();
        #pragma unroll
        for (int o = 1; o < 256; o <<= 1) {
            int v = (t >= o) ? sh[t - o] : 0;
            __syncthreads();
            sh[t] += v;
            __syncthreads();
        }
        if (t < SCAN_NB) g_boff[t] = sh[t] - v0;
    } else {
        gemm1_tile(blockIdx.x - 1 + G_K2 + G_K3, x, W1);
    }
}

// ---------------- K5: scan3 | gemm chunk 4 ----------------
__global__ void k5_scan3_gemm(const float* __restrict__ x, const float* __restrict__ W1) {
    if (blockIdx.x < SCAN3_NB) {
        int i = blockIdx.x * 256 + threadIdx.x;
        if (i < N_NODES) {
            int off = g_scan[i] + g_boff[i / SCAN_ELEMS];
            g_rowptr[i] = off;
            g_cursor[i] = off;
            g_dinv[i]   = rsqrtf((float)g_deg[i]);
        }
        if (i == 0) g_rowptr[N_NODES] = N_EDGES;
    } else {
        gemm1_tile(blockIdx.x - SCAN3_NB + G_K2 + G_K3 + G_K4, x, W1);
    }
}

// ---------------- K6: scatter | gemm chunk 5 ----------------
__global__ void k6_scatter_gemm(const void* __restrict__ ei,
                                const float* __restrict__ x, const float* __restrict__ W1) {
    if (blockIdx.x < SCAT_BLKS) {
        int e = blockIdx.x * 256 + threadIdx.x;
        int s = edge_at(ei, e);
        int d = edge_at(ei, (long long)N_EDGES + e);
        int pos = atomicAdd(&g_cursor[d], 1);
        g_csr[pos] = s;
    } else {
        gemm1_tile(blockIdx.x - SCAT_BLKS + G_K2 + G_K3 + G_K4 + G_K5, x, W1);
    }
}

// ---------------- K7: h1 *= dinv[node] (join point) ----------------
__global__ void k7_scale() {
    int idx = blockIdx.x * 256 + threadIdx.x;      // float2 index, 3.2M total
    float di = g_dinv[idx >> 5];
    float2 v = ((float2*)g_h1)[idx];
    v.x *= di; v.y *= di;
    ((float2*)g_h1)[idx] = v;
}

// ---------------- K8: agg1 fused with layer-2 channel fold ----------------
__global__ void k8_agg1(const float* __restrict__ b1) {
    int warp = threadIdx.x >> 5, lane = threadIdx.x & 31;
    int node = blockIdx.x * 8 + warp;
    if (node >= N_NODES) return;

    const float2* __restrict__ h2 = (const float2*)g_h1;
    int rbeg = g_rowptr[node];
    int rend = g_rowptr[node + 1];
    float2 acc = make_float2(0.f, 0.f);
    #pragma unroll 4
    for (int e = rbeg; e < rend; e++) {
        int s = g_csr[e];                        // uniform: broadcast
        float2 v = h2[s * 32 + lane];            // 256B row gather (L2-resident)
        acc.x += v.x;
        acc.y += v.y;
    }
    float2 sv = h2[node * 32 + lane];            // self term (already dinv-scaled)
    acc.x += sv.x;
    acc.y += sv.y;

    float di = g_dinv[node];
    float2 bb = ((const float2*)b1)[lane];
    float ax = fmaxf(fmaf(di, acc.x, bb.x), 0.f);
    float ay = fmaxf(fmaf(di, acc.y, bb.y), 0.f);

    float2 wv = ((const float2*)g_w)[lane];
    float p = ax * wv.x + ay * wv.y;
    #pragma unroll
    for (int o = 16; o > 0; o >>= 1) p += __shfl_xor_sync(0xffffffffu, p, o);
    if (lane == 0) g_z[node] = di * p;
}

// ---------------- K9: scalar agg + classifier const ----------------
__global__ void k9_agg2(float* __restrict__ out) {
    int warp = threadIdx.x >> 5, lane = threadIdx.x & 31;
    int node = blockIdx.x * 8 + warp;
    if (node >= N_NODES) return;

    int rbeg = g_rowptr[node];
    int rend = g_rowptr[node + 1];
    float acc = 0.f;
    for (int e = rbeg + lane; e < rend; e += 32) {
        acc += g_z[g_csr[e]];
    }
    #pragma unroll
    for (int o = 16; o > 0; o >>= 1) acc += __shfl_xor_sync(0xffffffffu, acc, o);
    if (lane == 0) out[node] = g_dinv[node] * (acc + g_z[node]) + g_cb;
}

// ---------------- launch ----------------
extern "C" void kernel_launch(void* const* d_in, const int* in_sizes, int n_in,
                              void* d_out, int out_size) {
    const float* x  = (const float*)d_in[0];
    const void*  ei = d_in[1];
    const float* W1 = (const float*)d_in[2];
    const float* b1 = (const float*)d_in[3];
    const float* W2 = (const float*)d_in[4];
    const float* b2 = (const float*)d_in[5];
    const float* Wc = (const float*)d_in[6];
    const float* bc = (const float*)d_in[7];
    float* out = (float*)d_out;

    k1_init        <<<SCAN3_NB + 2,        256>>>((const unsigned*)ei, W2, b2, Wc, bc);
    k2_hist_gemm   <<<HIST_BLKS + G_K2,    256>>>(ei, x, W1);
    k3_scan1_gemm  <<<SCAN_NB + G_K3,      256>>>(x, W1);
    k4_scan2_gemm  <<<1 + G_K4,            256>>>(x, W1);
    k5_scan3_gemm  <<<SCAN3_NB + G_K5,     256>>>(x, W1);
    k6_scatter_gemm<<<SCAT_BLKS + G_K6,    256>>>(ei, x, W1);
    k7_scale       <<<(N_NODES * 32) / 256, 256>>>();
    k8_agg1        <<<(N_NODES + 7) / 8,   256>>>(b1);
    k9_agg2        <<<(N_NODES + 7) / 8,   256>>>(out);
}

// round 6
// speedup vs baseline: 1.1559x; 1.1559x over previous
#include <cuda_runtime.h>
#include <cuda_fp16.h>

#define N_NODES 100000
#define N_EDGES 3200000
#define IN_DIM  128
#define HID     64

#define SCAN_B  512
#define SCAN_NB ((N_NODES + SCAN_B - 1) / SCAN_B)   // 196

// ---------------- scratch (device globals; no allocation allowed) ----------------
__device__ int     g_is64;                  // 1 if edge_index is int64, 0 if int32
__device__ int     g_deg[N_NODES];
__device__ float   g_dinv[N_NODES];
__device__ int     g_rowptr[N_NODES + 1];
__device__ int     g_cursor[N_NODES];
__device__ int     g_scan[N_NODES];
__device__ int     g_bsum[SCAN_NB];
__device__ int     g_boff[SCAN_NB];
__device__ int     g_csr[N_EDGES];          // src index only
__device__ __half2 g_h1h[N_NODES * (HID/2)];// h1' = dinv * (x @ W1^T), fp16
__device__ float   g_z[N_NODES];            // z'  = dinv * (a1 . w)
__device__ float   g_w[HID];                // w = W2^T @ Wc
__device__ float   g_cb;                    // b2.Wc + bc

// ---------------- dtype probe ----------------
// int64 edge ids in [0,100000) => every odd 32-bit word is 0.
__global__ void detect_kernel(const unsigned* __restrict__ ei32) {
    unsigned o = 0;
    #pragma unroll
    for (int i = 1; i < 128; i += 2) o |= ei32[i];
    g_is64 = (o == 0) ? 1 : 0;
}

__device__ __forceinline__ int edge_at(const void* ei, long long idx) {
    if (g_is64) return (int)((const long long*)ei)[idx];
    return ((const int*)ei)[idx];
}

// ---------------- degree init (self-loop counts as 1) ----------------
__global__ void init_deg_kernel() {
    int i = blockIdx.x * blockDim.x + threadIdx.x;
    if (i < N_NODES) g_deg[i] = 1;
}

// ---------------- dst-degree histogram ----------------
__global__ void hist_kernel(const void* __restrict__ ei) {
    int e = blockIdx.x * blockDim.x + threadIdx.x;
    if (e < N_EDGES) {
        int d = edge_at(ei, (long long)N_EDGES + e);
        atomicAdd(&g_deg[d], 1);
    }
}

// ---------------- parallel 3-phase exclusive scan of (deg-1) ----------------
__global__ void scan1_kernel() {
    __shared__ int wsum[16];
    const int tid  = threadIdx.x;
    const int lane = tid & 31, warp = tid >> 5;
    const int i = blockIdx.x * SCAN_B + tid;
    int v = (i < N_NODES) ? (g_deg[i] - 1) : 0;
    int s = v;
    #pragma unroll
    for (int o = 1; o < 32; o <<= 1) {
        int t = __shfl_up_sync(0xffffffffu, s, o);
        if (lane >= o) s += t;
    }
    if (lane == 31) wsum[warp] = s;
    __syncthreads();
    if (warp == 0) {
        int ws = (lane < 16) ? wsum[lane] : 0;
        #pragma unroll
        for (int o = 1; o < 16; o <<= 1) {
            int t = __shfl_up_sync(0xffffffffu, ws, o);
            if (lane >= o) ws += t;
        }
        if (lane < 16) wsum[lane] = ws;
    }
    __syncthreads();
    int excl = s - v + (warp ? wsum[warp - 1] : 0);
    if (i < N_NODES) g_scan[i] = excl;
    if (tid == SCAN_B - 1) g_bsum[blockIdx.x] = excl + v;
}

__global__ void scan2_kernel() {       // 1 block, 256 threads (>=196)
    __shared__ int sh[256];
    const int t = threadIdx.x;
    int v0 = (t < SCAN_NB) ? g_bsum[t] : 0;
    sh[t] = v0;
    __syncthreads();
    #pragma unroll
    for (int o = 1; o < 256; o <<= 1) {
        int v = (t >= o) ? sh[t - o] : 0;
        __syncthreads();
        sh[t] += v;
        __syncthreads();
    }
    if (t < SCAN_NB) g_boff[t] = sh[t] - v0;
}

__global__ void scan3_kernel() {
    int i = blockIdx.x * blockDim.x + threadIdx.x;
    if (i < N_NODES) {
        int off = g_scan[i] + g_boff[i / SCAN_B];
        g_rowptr[i] = off;
        g_cursor[i] = off;
        g_dinv[i]   = rsqrtf((float)g_deg[i]);
    }
    if (i == 0) g_rowptr[N_NODES] = N_EDGES;   // sum(deg-1) == E
}

// ---------------- counting-sort scatter: CSR of src indices ----------------
__global__ void scatter_kernel(const void* __restrict__ ei) {
    int e = blockIdx.x * blockDim.x + threadIdx.x;
    if (e < N_EDGES) {
        int s = edge_at(ei, e);
        int d = edge_at(ei, (long long)N_EDGES + e);
        int pos = atomicAdd(&g_cursor[d], 1);
        g_csr[pos] = s;
    }
}

// ---------------- classifier fold: w = W2^T @ Wc, cb = b2.Wc + bc ----------------
__global__ void wprep_kernel(const float* __restrict__ W2,
                             const float* __restrict__ b2,
                             const float* __restrict__ Wc,
                             const float* __restrict__ bc) {
    int k = threadIdx.x;              // 64 threads
    float s = 0.f;
    #pragma unroll
    for (int j = 0; j < HID; j++) s = fmaf(Wc[j], W2[j * HID + k], s);
    g_w[k] = s;
    if (k == 0) {
        float c = bc[0];
        #pragma unroll
        for (int j = 0; j < HID; j++) c = fmaf(b2[j], Wc[j], c);
        g_cb = c;
    }
}

// ---------------- GEMM1: h1'[n][o] = fp16( dinv[n] * sum_k x[n][k]*W1[o][k] ) ----------------
// Block: 256 threads = 8 warps; warp computes 4 nodes x 64 outputs (2 per lane).
__global__ void gemm1_kernel(const float* __restrict__ X, const float* __restrict__ W) {
    __shared__ __align__(16) float Ws[64 * 66];   // [kk][o] transposed, padded
    __shared__ __align__(16) float Xs[32 * 64];   // [node_local][kk]

    const int tid  = threadIdx.x;
    const int warp = tid >> 5, lane = tid & 31;
    const int node0 = blockIdx.x * 32;

    float2 acc[4];
    #pragma unroll
    for (int r = 0; r < 4; r++) acc[r] = make_float2(0.f, 0.f);

    #pragma unroll
    for (int kt = 0; kt < IN_DIM; kt += 64) {
        #pragma unroll
        for (int i = tid; i < 64 * 64; i += 256) {
            int o = i >> 6, kk = i & 63;
            Ws[kk * 66 + o] = W[o * IN_DIM + kt + kk];
        }
        #pragma unroll
        for (int i = tid; i < 32 * 64; i += 256) {
            int nl = i >> 6, kk = i & 63;
            Xs[nl * 64 + kk] = X[(node0 + nl) * IN_DIM + kt + kk];
        }
        __syncthreads();
        #pragma unroll 8
        for (int kk = 0; kk < 64; kk++) {
            float2 w = *(const float2*)&Ws[kk * 66 + 2 * lane];
            #pragma unroll
            for (int r = 0; r < 4; r++) {
                float xv = Xs[(warp * 4 + r) * 64 + kk];
                acc[r].x = fmaf(xv, w.x, acc[r].x);
                acc[r].y = fmaf(xv, w.y, acc[r].y);
            }
        }
        __syncthreads();
    }
    #pragma unroll
    for (int r = 0; r < 4; r++) {
        int node = node0 + warp * 4 + r;
        float di = g_dinv[node];
        g_h1h[node * 32 + lane] = __floats2half2_rn(acc[r].x * di, acc[r].y * di);
    }
}

// ---------------- agg1 fused with layer-2 channel fold (fp16 gathers) ----------------
// a1[d] = relu(dinv_d*(sum_s h1'[s] + h1'[d]) + b1);  z'[d] = dinv_d * (a1[d].w)
__global__ void agg1_kernel(const float* __restrict__ b1) {
    int warp = threadIdx.x >> 5, lane = threadIdx.x & 31;
    int node = blockIdx.x * 8 + warp;
    if (node >= N_NODES) return;

    const __half2* __restrict__ h2 = g_h1h;
    int rbeg = g_rowptr[node];
    int rend = g_rowptr[node + 1];
    float2 acc = make_float2(0.f, 0.f);
    #pragma unroll 4
    for (int e = rbeg; e < rend; e++) {
        int s = g_csr[e];                        // uniform address: broadcast
        float2 v = __half22float2(h2[s * 32 + lane]);   // 128B row gather
        acc.x += v.x;
        acc.y += v.y;
    }
    float2 sv = __half22float2(h2[node * 32 + lane]);   // self term (dinv-scaled)
    acc.x += sv.x;
    acc.y += sv.y;

    float di = g_dinv[node];
    float2 bb = ((const float2*)b1)[lane];
    float ax = fmaxf(fmaf(di, acc.x, bb.x), 0.f);
    float ay = fmaxf(fmaf(di, acc.y, bb.y), 0.f);

    float2 wv = ((const float2*)g_w)[lane];
    float p = ax * wv.x + ay * wv.y;
    #pragma unroll
    for (int o = 16; o > 0; o >>= 1) p += __shfl_xor_sync(0xffffffffu, p, o);
    if (lane == 0) g_z[node] = di * p;           // z' = dinv * (a1 . w)
}

// ---------------- agg2 (scalar): out[d] = dinv_d*(sum_s z'[s] + z'[d]) + cb ----------------
__global__ void agg2_kernel(float* __restrict__ out) {
    int warp = threadIdx.x >> 5, lane = threadIdx.x & 31;
    int node = blockIdx.x * 8 + warp;
    if (node >= N_NODES) return;

    int rbeg = g_rowptr[node];
    int rend = g_rowptr[node + 1];
    float acc = 0.f;
    for (int e = rbeg + lane; e < rend; e += 32) {
        acc += g_z[g_csr[e]];                    // 4B gather in 400KB table
    }
    #pragma unroll
    for (int o = 16; o > 0; o >>= 1) acc += __shfl_xor_sync(0xffffffffu, acc, o);
    if (lane == 0) out[node] = g_dinv[node] * (acc + g_z[node]) + g_cb;
}

// ---------------- launch ----------------
extern "C" void kernel_launch(void* const* d_in, const int* in_sizes, int n_in,
                              void* d_out, int out_size) {
    const float* x  = (const float*)d_in[0];
    const void*  ei = d_in[1];                 // int32 or int64, probed on device
    const float* W1 = (const float*)d_in[2];
    const float* b1 = (const float*)d_in[3];
    const float* W2 = (const float*)d_in[4];
    const float* b2 = (const float*)d_in[5];
    const float* Wc = (const float*)d_in[6];
    const float* bc = (const float*)d_in[7];
    float* out = (float*)d_out;

    detect_kernel<<<1, 1>>>((const unsigned*)ei);
    init_deg_kernel<<<(N_NODES + 511) / 512, 512>>>();
    hist_kernel<<<N_EDGES / 256, 256>>>(ei);
    scan1_kernel<<<SCAN_NB, SCAN_B>>>();
    scan2_kernel<<<1, 256>>>();
    scan3_kernel<<<(N_NODES + 511) / 512, 512>>>();
    scatter_kernel<<<N_EDGES / 256, 256>>>(ei);

    wprep_kernel<<<1, 64>>>(W2, b2, Wc, bc);
    gemm1_kernel<<<N_NODES / 32, 256>>>(x, W1);
    agg1_kernel<<<(N_NODES + 7) / 8, 256>>>(b1);
    agg2_kernel<<<(N_NODES + 7) / 8, 256>>>(out);
}

// round 7
// speedup vs baseline: 1.3794x; 1.1934x over previous
#include <cuda_runtime.h>
#include <cuda_fp16.h>

#define N_NODES 100000
#define N_EDGES 3200000
#define IN_DIM  128
#define HID     64

#define SCAN_B  512
#define SCAN_NB ((N_NODES + SCAN_B - 1) / SCAN_B)   // 196

// ---------------- scratch (device globals; no allocation allowed) ----------------
__device__ int     g_is64;                  // 1 if edge_index is int64, 0 if int32
__device__ int     g_deg[N_NODES];
__device__ float   g_dinv[N_NODES];
__device__ int     g_rowptr[N_NODES + 1];
__device__ int     g_cursor[N_NODES];
__device__ int     g_scan[N_NODES];
__device__ int     g_bsum[SCAN_NB];
__device__ int     g_boff[SCAN_NB];
__device__ int     g_csr[N_EDGES];          // src index only
__device__ __half2 g_h1h[N_NODES * (HID/2)];// h1' = dinv * (x @ W1^T), fp16
__device__ float   g_z[N_NODES];            // z'  = dinv * (a1 . w)
__device__ float   g_w[HID];                // w = W2^T @ Wc
__device__ float   g_cb;                    // b2.Wc + bc

// ---------------- dtype probe ----------------
__global__ void detect_kernel(const unsigned* __restrict__ ei32) {
    unsigned o = 0;
    #pragma unroll
    for (int i = 1; i < 128; i += 2) o |= ei32[i];
    g_is64 = (o == 0) ? 1 : 0;
}

__device__ __forceinline__ int edge_at(const void* ei, long long idx) {
    if (g_is64) return (int)((const long long*)ei)[idx];
    return ((const int*)ei)[idx];
}

// ---------------- degree init (self-loop counts as 1) ----------------
__global__ void init_deg_kernel() {
    int i = blockIdx.x * blockDim.x + threadIdx.x;
    if (i < N_NODES) g_deg[i] = 1;
}

// ---------------- dst-degree histogram ----------------
__global__ void hist_kernel(const void* __restrict__ ei) {
    int e = blockIdx.x * blockDim.x + threadIdx.x;
    if (e < N_EDGES) {
        int d = edge_at(ei, (long long)N_EDGES + e);
        atomicAdd(&g_deg[d], 1);
    }
}

// ---------------- parallel 3-phase exclusive scan of (deg-1) ----------------
__global__ void scan1_kernel() {
    __shared__ int wsum[16];
    const int tid  = threadIdx.x;
    const int lane = tid & 31, warp = tid >> 5;
    const int i = blockIdx.x * SCAN_B + tid;
    int v = (i < N_NODES) ? (g_deg[i] - 1) : 0;
    int s = v;
    #pragma unroll
    for (int o = 1; o < 32; o <<= 1) {
        int t = __shfl_up_sync(0xffffffffu, s, o);
        if (lane >= o) s += t;
    }
    if (lane == 31) wsum[warp] = s;
    __syncthreads();
    if (warp == 0) {
        int ws = (lane < 16) ? wsum[lane] : 0;
        #pragma unroll
        for (int o = 1; o < 16; o <<= 1) {
            int t = __shfl_up_sync(0xffffffffu, ws, o);
            if (lane >= o) ws += t;
        }
        if (lane < 16) wsum[lane] = ws;
    }
    __syncthreads();
    int excl = s - v + (warp ? wsum[warp - 1] : 0);
    if (i < N_NODES) g_scan[i] = excl;
    if (tid == SCAN_B - 1) g_bsum[blockIdx.x] = excl + v;
}

__global__ void scan2_kernel() {       // 1 block, 256 threads (>=196)
    __shared__ int sh[256];
    const int t = threadIdx.x;
    int v0 = (t < SCAN_NB) ? g_bsum[t] : 0;
    sh[t] = v0;
    __syncthreads();
    #pragma unroll
    for (int o = 1; o < 256; o <<= 1) {
        int v = (t >= o) ? sh[t - o] : 0;
        __syncthreads();
        sh[t] += v;
        __syncthreads();
    }
    if (t < SCAN_NB) g_boff[t] = sh[t] - v0;
}

__global__ void scan3_kernel() {
    int i = blockIdx.x * blockDim.x + threadIdx.x;
    if (i < N_NODES) {
        int off = g_scan[i] + g_boff[i / SCAN_B];
        g_rowptr[i] = off;
        g_cursor[i] = off;
        g_dinv[i]   = rsqrtf((float)g_deg[i]);
    }
    if (i == 0) g_rowptr[N_NODES] = N_EDGES;   // sum(deg-1) == E
}

// ---------------- counting-sort scatter: CSR of src indices ----------------
__global__ void scatter_kernel(const void* __restrict__ ei) {
    int e = blockIdx.x * blockDim.x + threadIdx.x;
    if (e < N_EDGES) {
        int s = edge_at(ei, e);
        int d = edge_at(ei, (long long)N_EDGES + e);
        int pos = atomicAdd(&g_cursor[d], 1);
        g_csr[pos] = s;
    }
}

// ---------------- classifier fold: w = W2^T @ Wc, cb = b2.Wc + bc ----------------
__global__ void wprep_kernel(const float* __restrict__ W2,
                             const float* __restrict__ b2,
                             const float* __restrict__ Wc,
                             const float* __restrict__ bc) {
    int k = threadIdx.x;              // 64 threads
    float s = 0.f;
    #pragma unroll
    for (int j = 0; j < HID; j++) s = fmaf(Wc[j], W2[j * HID + k], s);
    g_w[k] = s;
    if (k == 0) {
        float c = bc[0];
        #pragma unroll
        for (int j = 0; j < HID; j++) c = fmaf(b2[j], Wc[j], c);
        g_cb = c;
    }
}

// ---------------- tf32 helpers ----------------
__device__ __forceinline__ unsigned f2tf(float f) {
    unsigned u;
    asm("cvt.rna.tf32.f32 %0, %1;" : "=r"(u) : "f"(f));
    return u;
}

__device__ __forceinline__ void mma_tf32(float* c,
                                         unsigned a0, unsigned a1, unsigned a2, unsigned a3,
                                         unsigned b0, unsigned b1) {
    asm volatile(
        "mma.sync.aligned.m16n8k8.row.col.f32.tf32.tf32.f32 "
        "{%0,%1,%2,%3},{%4,%5,%6,%7},{%8,%9},{%0,%1,%2,%3};"
        : "+f"(c[0]), "+f"(c[1]), "+f"(c[2]), "+f"(c[3])
        : "r"(a0), "r"(a1), "r"(a2), "r"(a3), "r"(b0), "r"(b1));
}

// ---------------- GEMM1 (tensor core, tf32): h1' = fp16(dinv * (x @ W1^T)) ----------------
// Block 256 thr = 8 warps. Block tile: 64 nodes x 64 channels. Warp: 16 nodes x 32 ch.
// K processed in two smem tiles of 64. Padded stride 68 -> conflict-free fragment LDS.
#define GPAD 68
__global__ void gemm1_kernel(const float* __restrict__ X, const float* __restrict__ W) {
    __shared__ unsigned As[64 * GPAD];   // A tile (tf32 bits), [node_local][k]
    __shared__ unsigned Ws[64 * GPAD];   // W tile (tf32 bits), [out_ch][k]

    const int tid  = threadIdx.x;
    const int warp = tid >> 5, lane = tid & 31;
    const int g    = lane >> 2, tig = lane & 3;      // groupID, threadID_in_group
    const int m0   = (warp >> 1) * 16;               // warp row base in block tile
    const int nb   = (warp & 1) * 32;                // warp col base
    const int node0 = blockIdx.x * 64;

    float c[4][4];
    #pragma unroll
    for (int nt = 0; nt < 4; nt++)
        #pragma unroll
        for (int j = 0; j < 4; j++) c[nt][j] = 0.f;

    #pragma unroll
    for (int kt = 0; kt < IN_DIM; kt += 64) {
        // load A tile: 64 rows x 64 k (clamp rows for tail block)
        #pragma unroll
        for (int i = tid; i < 64 * 64; i += 256) {
            int r = i >> 6, k = i & 63;
            int node = node0 + r;
            if (node > N_NODES - 1) node = N_NODES - 1;
            As[r * GPAD + k] = f2tf(X[node * IN_DIM + kt + k]);
        }
        // load W tile: 64 out x 64 k
        #pragma unroll
        for (int i = tid; i < 64 * 64; i += 256) {
            int r = i >> 6, k = i & 63;
            Ws[r * GPAD + k] = f2tf(W[r * IN_DIM + kt + k]);
        }
        __syncthreads();

        #pragma unroll
        for (int ks = 0; ks < 8; ks++) {
            int k0 = ks * 8;
            unsigned a0 = As[(m0 + g)     * GPAD + k0 + tig];
            unsigned a1 = As[(m0 + g + 8) * GPAD + k0 + tig];
            unsigned a2 = As[(m0 + g)     * GPAD + k0 + tig + 4];
            unsigned a3 = As[(m0 + g + 8) * GPAD + k0 + tig + 4];
            #pragma unroll
            for (int nt = 0; nt < 4; nt++) {
                int n0 = nb + nt * 8;
                unsigned b0 = Ws[(n0 + g) * GPAD + k0 + tig];
                unsigned b1 = Ws[(n0 + g) * GPAD + k0 + tig + 4];
                mma_tf32(c[nt], a0, a1, a2, a3, b0, b1);
            }
        }
        __syncthreads();
    }

    // epilogue: scale by dinv, convert fp16, store.
    // c[nt]: {c0,c1} -> node (m0+g), cols nb+nt*8+2*tig, +1 ; {c2,c3} -> node+8.
    int nodeA = node0 + m0 + g;
    int nodeB = nodeA + 8;
    int colh  = (nb >> 1) + tig;                     // half2 col base offset within 32
    if (nodeA < N_NODES) {
        float di = g_dinv[nodeA];
        #pragma unroll
        for (int nt = 0; nt < 4; nt++)
            g_h1h[nodeA * 32 + colh + nt * 4] = __floats2half2_rn(c[nt][0] * di, c[nt][1] * di);
    }
    if (nodeB < N_NODES) {
        float di = g_dinv[nodeB];
        #pragma unroll
        for (int nt = 0; nt < 4; nt++)
            g_h1h[nodeB * 32 + colh + nt * 4] = __floats2half2_rn(c[nt][2] * di, c[nt][3] * di);
    }
}

// ---------------- agg1: 4 edges per warp-instruction, fused layer-2 fold ----------------
// lane = g*8 + c : g in [0,4) picks edge within quad, c in [0,8) picks 8-channel slice.
__global__ void agg1_kernel(const float* __restrict__ b1) {
    int warp = threadIdx.x >> 5, lane = threadIdx.x & 31;
    int node = blockIdx.x * 8 + warp;
    if (node >= N_NODES) return;

    const int g = lane >> 3, c = lane & 7;
    const uint4* __restrict__ h4 = (const uint4*)g_h1h;   // 8 channels per uint4

    int rbeg = g_rowptr[node];
    int rend = g_rowptr[node + 1];

    float acc[8];
    #pragma unroll
    for (int j = 0; j < 8; j++) acc[j] = 0.f;

    for (int eb = rbeg; eb < rend; eb += 4) {
        int e = eb + g;
        if (e < rend) {
            int s = g_csr[e];
            uint4 v = h4[s * 8 + c];
            const __half2* hp = (const __half2*)&v;
            #pragma unroll
            for (int j = 0; j < 4; j++) {
                float2 f = __half22float2(hp[j]);
                acc[2 * j]     += f.x;
                acc[2 * j + 1] += f.y;
            }
        }
    }
    // reduce across the 4 edge-groups (lanes differing in bits 3,4)
    #pragma unroll
    for (int j = 0; j < 8; j++) {
        acc[j] += __shfl_xor_sync(0xffffffffu, acc[j], 8);
        acc[j] += __shfl_xor_sync(0xffffffffu, acc[j], 16);
    }
    // self term
    {
        uint4 v = h4[node * 8 + c];
        const __half2* hp = (const __half2*)&v;
        #pragma unroll
        for (int j = 0; j < 4; j++) {
            float2 f = __half22float2(hp[j]);
            acc[2 * j]     += f.x;
            acc[2 * j + 1] += f.y;
        }
    }

    float di = g_dinv[node];
    float4 bb0 = ((const float4*)b1)[c * 2];
    float4 bb1 = ((const float4*)b1)[c * 2 + 1];
    float4 wv0 = ((const float4*)g_w)[c * 2];
    float4 wv1 = ((const float4*)g_w)[c * 2 + 1];
    const float* bbp = (const float*)&bb0;   // bb0,bb1 contiguous on stack
    float bb[8] = {bb0.x, bb0.y, bb0.z, bb0.w, bb1.x, bb1.y, bb1.z, bb1.w};
    float wv[8] = {wv0.x, wv0.y, wv0.z, wv0.w, wv1.x, wv1.y, wv1.z, wv1.w};
    (void)bbp;

    float p = 0.f;
    #pragma unroll
    for (int j = 0; j < 8; j++) {
        float a = fmaxf(fmaf(di, acc[j], bb[j]), 0.f);
        p = fmaf(a, wv[j], p);
    }
    // reduce across the 8 channel-slices (lanes differing in bits 0..2)
    p += __shfl_xor_sync(0xffffffffu, p, 1);
    p += __shfl_xor_sync(0xffffffffu, p, 2);
    p += __shfl_xor_sync(0xffffffffu, p, 4);
    if (lane == 0) g_z[node] = di * p;           // z' = dinv * (a1 . w)
}

// ---------------- agg2 (scalar): out[d] = dinv_d*(sum_s z'[s] + z'[d]) + cb ----------------
__global__ void agg2_kernel(float* __restrict__ out) {
    int warp = threadIdx.x >> 5, lane = threadIdx.x & 31;
    int node = blockIdx.x * 8 + warp;
    if (node >= N_NODES) return;

    int rbeg = g_rowptr[node];
    int rend = g_rowptr[node + 1];
    float acc = 0.f;
    for (int e = rbeg + lane; e < rend; e += 32) {
        acc += g_z[g_csr[e]];
    }
    #pragma unroll
    for (int o = 16; o > 0; o >>= 1) acc += __shfl_xor_sync(0xffffffffu, acc, o);
    if (lane == 0) out[node] = g_dinv[node] * (acc + g_z[node]) + g_cb;
}

// ---------------- launch ----------------
extern "C" void kernel_launch(void* const* d_in, const int* in_sizes, int n_in,
                              void* d_out, int out_size) {
    const float* x  = (const float*)d_in[0];
    const void*  ei = d_in[1];                 // int32 or int64, probed on device
    const float* W1 = (const float*)d_in[2];
    const float* b1 = (const float*)d_in[3];
    const float* W2 = (const float*)d_in[4];
    const float* b2 = (const float*)d_in[5];
    const float* Wc = (const float*)d_in[6];
    const float* bc = (const float*)d_in[7];
    float* out = (float*)d_out;

    detect_kernel<<<1, 1>>>((const unsigned*)ei);
    init_deg_kernel<<<(N_NODES + 511) / 512, 512>>>();
    hist_kernel<<<N_EDGES / 256, 256>>>(ei);
    scan1_kernel<<<SCAN_NB, SCAN_B>>>();
    scan2_kernel<<<1, 256>>>();
    scan3_kernel<<<(N_NODES + 511) / 512, 512>>>();
    scatter_kernel<<<N_EDGES / 256, 256>>>(ei);

    wprep_kernel<<<1, 64>>>(W2, b2, Wc, bc);
    gemm1_kernel<<<(N_NODES + 63) / 64, 256>>>(x, W1);
    agg1_kernel<<<(N_NODES + 7) / 8, 256>>>(b1);
    agg2_kernel<<<(N_NODES + 7) / 8, 256>>>(out);
}